// round 14
// baseline (speedup 1.0000x reference)
#include <cuda_runtime.h>
#include <cstdint>
#include <cmath>

// ===========================================================================
// MultiheadChannelAttention — Round 10: int8 two-limb (15-bit) GEMMs via
// mma.sync.m16n8k32.s8 (2x MAC/instr vs bf16).  x ~= s*hi + (s/128)*lo,
// C = sA*sB*(P1 + (P2+P3)/128); P1, P23 exact int32 accumulators.
// All GEMMs NT: C[M,N] = alpha * A[M,K] @ B[N,K]^T, fp32 out.
// ===========================================================================

// ------------------------- sizes (elements) --------------------------------
constexpr long long R_EMB  = 8LL*1024;          // rows of emb tensors
constexpr long long N_EMBA = 8LL*1024*960;
constexpr long long N_WK   = 4LL*960*960;
constexpr long long N_KT   = 32LL*960*1024;     // 30720 rows x 1024
constexpr long long N_VV   = 32LL*1024*960;     // 32768 rows x 960
constexpr long long N_Qmx  = 32LL*512*1024;     // 16384 rows x 1024 (max)
constexpr long long N_Amx  = 32LL*512*960;      // 16384 rows x 960 (max)
constexpr long long N_CMmx = 8LL*1024*512;      // 8192 rows x 512 (max)
constexpr long long N_TMP  = 32LL*1024*1024;    // fp32 staging (max)

// ------------------------- device scratch ----------------------------------
// int8 quant buffers: hi at [0..n), lo at [n..2n); scales separate fp32.
__device__ __align__(128) int8_t g_q_emb1[2*(R_EMB*64)];
__device__ __align__(128) int8_t g_q_emb2[2*(R_EMB*128)];
__device__ __align__(128) int8_t g_q_emb3[2*(R_EMB*256)];
__device__ __align__(128) int8_t g_q_emb4[2*(R_EMB*512)];
__device__ __align__(128) int8_t g_q_emba[2*N_EMBA];
__device__ __align__(128) int8_t g_q_wq1[2*(4LL*64*64)];
__device__ __align__(128) int8_t g_q_wq2[2*(4LL*128*128)];
__device__ __align__(128) int8_t g_q_wq3[2*(4LL*256*256)];
__device__ __align__(128) int8_t g_q_wq4[2*(4LL*512*512)];
__device__ __align__(128) int8_t g_q_wk [2*N_WK];
__device__ __align__(128) int8_t g_q_wv [2*N_WK];
__device__ __align__(128) int8_t g_q_wo1[2*(64LL*64)];
__device__ __align__(128) int8_t g_q_wo2[2*(128LL*128)];
__device__ __align__(128) int8_t g_q_wo3[2*(256LL*256)];
__device__ __align__(128) int8_t g_q_wo4[2*(512LL*512)];
__device__ __align__(128) int8_t g_q_kt [2*N_KT];
__device__ __align__(128) int8_t g_q_v  [2*N_VV];
__device__ __align__(128) int8_t g_q_q  [2*N_Qmx];
__device__ __align__(128) int8_t g_q_a  [2*N_Amx];
__device__ __align__(128) int8_t g_q_cm [2*N_CMmx];
// scales (per row)
__device__ float g_s_emb1[R_EMB], g_s_emb2[R_EMB], g_s_emb3[R_EMB], g_s_emb4[R_EMB];
__device__ float g_s_emba[R_EMB];
__device__ float g_s_wq1[4*64],  g_s_wq2[4*128], g_s_wq3[4*256], g_s_wq4[4*512];
__device__ float g_s_wk[4*960],  g_s_wv[4*960];
__device__ float g_s_wo1[64], g_s_wo2[128], g_s_wo3[256], g_s_wo4[512];
__device__ float g_s_kt[32*960], g_s_v[32*1024], g_s_q[32*512], g_s_a[32*512];
__device__ float g_s_cm[8*1024];
// fp32 staging + scores + context
__device__ float g_TMP[N_TMP];
__device__ float g_S[N_Amx];
__device__ float g_C[N_Qmx];
__device__ float g_invstd[32];

// ------------------------- helpers -----------------------------------------
__device__ __forceinline__ uint32_t smem_u32(const void* p){
    uint32_t a;
    asm("{ .reg .u64 t; cvta.to.shared.u64 t, %1; cvt.u32.u64 %0, t; }"
        : "=r"(a) : "l"(p));
    return a;
}
__device__ __forceinline__ void ldsm_x4(uint32_t a, uint32_t& r0, uint32_t& r1,
                                        uint32_t& r2, uint32_t& r3){
    asm volatile("ldmatrix.sync.aligned.m8n8.x4.shared.b16 {%0,%1,%2,%3}, [%4];"
                 : "=r"(r0), "=r"(r1), "=r"(r2), "=r"(r3) : "r"(a));
}
__device__ __forceinline__ void mma_s8(int* c, const uint32_t* a,
                                       uint32_t b0, uint32_t b1){
    asm volatile(
        "mma.sync.aligned.m16n8k32.row.col.s32.s8.s8.s32 "
        "{%0,%1,%2,%3}, {%4,%5,%6,%7}, {%8,%9}, {%0,%1,%2,%3};"
        : "+r"(c[0]), "+r"(c[1]), "+r"(c[2]), "+r"(c[3])
        : "r"(a[0]), "r"(a[1]), "r"(a[2]), "r"(a[3]), "r"(b0), "r"(b1));
}
__device__ __forceinline__ float clamp127(float v){
    return fminf(127.f, fmaxf(-127.f, v));
}

// ------------------------- tile geometry -----------------------------------
constexpr int BM = 128, BN = 128;                  // K-chunk = 64 int8
constexpr int ROWB = 80;                           // 64B data + 16B pad
constexpr int MAT = 128 * ROWB;                    // 10240 B
constexpr int OFF_AH = 0, OFF_AL = MAT, OFF_BH = 2*MAT, OFF_BL = 3*MAT;
constexpr int STAGE_BYTES = 4 * MAT;               // 40960 B
constexpr int DYN_SMEM = 2 * STAGE_BYTES;          // 81920 B
constexpr int NTHREADS = 256;

// ===========================================================================
// int8 two-limb batched NT GEMM. z-mode: 0 shared, 1 z/H, 2 z%H, 3 z.
// 8 warps (2m x 4n), warp tile 64x32.
// ===========================================================================
__global__ __launch_bounds__(NTHREADS, 1)
void gemm_i8(
    const int8_t* __restrict__ Ahi, const int8_t* __restrict__ Alo,
    const int8_t* __restrict__ Bhi, const int8_t* __restrict__ Blo,
    const float* __restrict__ scaleA, const float* __restrict__ scaleB,
    float* __restrict__ Cf,
    int M, int N, int K,
    long long aStride, long long bStride,
    long long aScaleStride, long long bScaleStride,
    int modeA, int modeB, int H, float alpha)
{
    extern __shared__ char dynsmem[];
    const uint32_t sb = smem_u32(dynsmem);

    const int tid  = threadIdx.x;
    const int wid  = tid >> 5;
    const int lane = tid & 31;
    const int wm   = wid >> 2;            // 0..1 -> m offset 64*wm
    const int wn   = wid & 3;             // 0..3 -> n offset 32*wn

    const int z  = blockIdx.z;
    const int zA = (modeA == 0) ? 0 : (modeA == 1) ? (z / H) : (modeA == 2) ? (z % H) : z;
    const int zB = (modeB == 0) ? 0 : (modeB == 1) ? (z / H) : (modeB == 2) ? (z % H) : z;
    const int8_t* pA[2] = { Ahi + (long long)zA * aStride, Alo + (long long)zA * aStride };
    const int8_t* pB[2] = { Bhi + (long long)zB * bStride, Blo + (long long)zB * bStride };
    const float* sAp = scaleA + (long long)zA * aScaleStride;
    const float* sBp = scaleB + (long long)zB * bScaleStride;

    const int m0 = blockIdx.y * BM;
    const int n0 = blockIdx.x * BN;
    const int NC = K >> 6;                // chunks of 64 int8

    auto load_stage = [&](int stage, int kc) {
        const int k0 = kc << 6;
        const uint32_t stb = sb + (uint32_t)(stage * STAGE_BYTES);
#pragma unroll
        for (int it = 0; it < 8; ++it) {
            const int idx = it * NTHREADS + tid;     // 0..2047
            const int mat = idx >> 9;                // 0..3: AH, AL, BH, BL
            const int rem = idx & 511;
            const int row = rem >> 2;                // 0..127
            const int seg = rem & 3;                 // 16B segment
            int g, lim; const int8_t* src;
            if (mat < 2) { g = m0 + row; lim = M; src = pA[mat]; }
            else         { g = n0 + row; lim = N; src = pB[mat - 2]; }
            const int valid = (g < lim);
            const uint32_t dst = stb + (uint32_t)(mat * MAT) + (uint32_t)(row * ROWB + seg * 16);
            const char* sp = (const char*)(src + (long long)(valid ? g : 0) * K + k0 + seg * 16);
            const uint32_t sz = valid ? 16u : 0u;
            asm volatile("cp.async.cg.shared.global [%0], [%1], 16, %2;"
                         :: "r"(dst), "l"(sp), "r"(sz));
        }
        asm volatile("cp.async.commit_group;" ::: "memory");
    };

    int accP1[4][4][4], accP23[4][4][4];
#pragma unroll
    for (int t = 0; t < 4; t++)
#pragma unroll
        for (int n = 0; n < 4; n++)
#pragma unroll
            for (int j = 0; j < 4; j++) { accP1[t][n][j] = 0; accP23[t][n][j] = 0; }

    load_stage(0, 0);
    if (NC > 1) load_stage(1, 1);

    const uint32_t lrow = (uint32_t)(lane & 15) * ROWB;
    const uint32_t lseg = (uint32_t)(lane >> 4) * 16;

    for (int kc = 0; kc < NC; ++kc) {
        if (kc + 2 <= NC) { asm volatile("cp.async.wait_group 1;" ::: "memory"); }
        else              { asm volatile("cp.async.wait_group 0;" ::: "memory"); }
        __syncthreads();

        const int st = kc & 1;
        const uint32_t stb = sb + (uint32_t)(st * STAGE_BYTES);
        const uint32_t aHb = stb + OFF_AH, aLb = stb + OFF_AL;
        const uint32_t bHb = stb + OFF_BH, bLb = stb + OFF_BL;

#pragma unroll
        for (int kk = 0; kk < 2; ++kk) {             // two k32 steps per chunk
            const uint32_t koff = (uint32_t)kk * 32 + lseg;
            const uint32_t aro0 = (uint32_t)(wm * 64) * ROWB + lrow + koff;
            const uint32_t bro0 = (uint32_t)(wn * 32) * ROWB + lrow + koff;

            uint32_t aH[4][4], bH[2][4];
#pragma unroll
            for (int t = 0; t < 4; ++t)
                ldsm_x4(aHb + aro0 + (uint32_t)(t * 16) * ROWB,
                        aH[t][0], aH[t][1], aH[t][2], aH[t][3]);
#pragma unroll
            for (int p = 0; p < 2; ++p)
                ldsm_x4(bHb + bro0 + (uint32_t)(p * 16) * ROWB,
                        bH[p][0], bH[p][1], bH[p][2], bH[p][3]);

            // term 1: hiA * hiB -> P1
#pragma unroll
            for (int p = 0; p < 2; ++p)
#pragma unroll
                for (int t = 0; t < 4; ++t) {
                    mma_s8(accP1[t][2*p],   aH[t], bH[p][0], bH[p][2]);
                    mma_s8(accP1[t][2*p+1], aH[t], bH[p][1], bH[p][3]);
                }

            uint32_t bL[2][4];
#pragma unroll
            for (int p = 0; p < 2; ++p)
                ldsm_x4(bLb + bro0 + (uint32_t)(p * 16) * ROWB,
                        bL[p][0], bL[p][1], bL[p][2], bL[p][3]);

            // term 2: hiA * loB -> P23
#pragma unroll
            for (int p = 0; p < 2; ++p)
#pragma unroll
                for (int t = 0; t < 4; ++t) {
                    mma_s8(accP23[t][2*p],   aH[t], bL[p][0], bL[p][2]);
                    mma_s8(accP23[t][2*p+1], aH[t], bL[p][1], bL[p][3]);
                }

            uint32_t aL[4][4];
#pragma unroll
            for (int t = 0; t < 4; ++t)
                ldsm_x4(aLb + aro0 + (uint32_t)(t * 16) * ROWB,
                        aL[t][0], aL[t][1], aL[t][2], aL[t][3]);

            // term 3: loA * hiB -> P23
#pragma unroll
            for (int p = 0; p < 2; ++p)
#pragma unroll
                for (int t = 0; t < 4; ++t) {
                    mma_s8(accP23[t][2*p],   aL[t], bH[p][0], bH[p][2]);
                    mma_s8(accP23[t][2*p+1], aL[t], bH[p][1], bH[p][3]);
                }
        }
        __syncthreads();
        if (kc + 2 < NC) load_stage(st, kc + 2);
    }

    // ------- epilogue: C = alpha * sA * sB * (P1 + P23/128) ---------------
    const int grp  = lane >> 2;
    const int tid4 = lane & 3;
#pragma unroll
    for (int t = 0; t < 4; ++t) {
#pragma unroll
        for (int n = 0; n < 4; ++n) {
            const int gn = n0 + wn * 32 + n * 8 + tid4 * 2;
            if (gn >= N) continue;
            const float sb0 = sBp[gn] * alpha;
            const float sb1 = sBp[gn + 1] * alpha;
#pragma unroll
            for (int half = 0; half < 2; ++half) {
                const int gm = m0 + wm * 64 + t * 16 + grp + half * 8;
                if (gm >= M) continue;
                const float sa = sAp[gm];
                const float p10 = (float)accP1[t][n][half*2+0];
                const float p11 = (float)accP1[t][n][half*2+1];
                const float p20 = (float)accP23[t][n][half*2+0];
                const float p21 = (float)accP23[t][n][half*2+1];
                const float v0 = sa * sb0 * (p10 + p20 * 0.0078125f);
                const float v1 = sa * sb1 * (p11 + p21 * 0.0078125f);
                const long long base = (long long)z * M * N + (long long)gm * N + gn;
                *reinterpret_cast<float2*>(Cf + base) = make_float2(v0, v1);
            }
        }
    }
}

// ===========================================================================
// row quantization: fp32 row -> int8 hi/lo + scale.  one block per row.
// ===========================================================================
__global__ __launch_bounds__(128) void quant_rows(
    const float* __restrict__ src, int8_t* __restrict__ hi,
    int8_t* __restrict__ lo, float* __restrict__ scale, int K)
{
    const long long row = blockIdx.x;
    const float* p = src + row * K;
    const int tid = threadIdx.x;

    float m = 0.f;
    for (int i = tid; i < K; i += 128) m = fmaxf(m, fabsf(p[i]));
    __shared__ float sh[128];
    sh[tid] = m; __syncthreads();
    for (int off = 64; off > 0; off >>= 1) {
        if (tid < off) sh[tid] = fmaxf(sh[tid], sh[tid + off]);
        __syncthreads();
    }
    m = sh[0];
    const float s   = m * (1.0f / 127.0f);
    const float inv = (m > 0.f) ? (127.0f / m) : 0.f;
    if (tid == 0) scale[row] = s;

    for (int i = tid; i < K; i += 128) {
        const float x = p[i];
        const float h = clamp127(rintf(x * inv));
        const float r = x - h * s;
        const float l = clamp127(rintf(r * inv * 128.0f));
        hi[row * K + i] = (int8_t)(int)h;
        lo[row * K + i] = (int8_t)(int)l;
    }
}

// ===========================================================================
// per-(b,h) biased variance over d x KV -> inv_std (mean cancels in softmax)
// ===========================================================================
__global__ __launch_bounds__(256) void stats_kernel(
    const float* __restrict__ S, float* __restrict__ invstd, int elems)
{
    const int bh = blockIdx.x;
    const float4* p = reinterpret_cast<const float4*>(S + (long long)bh * elems);
    const int n4 = elems >> 2;
    float s = 0.f, s2 = 0.f;
    for (int i = threadIdx.x; i < n4; i += 256) {
        float4 v = p[i];
        s  += v.x + v.y + v.z + v.w;
        s2 += v.x * v.x + v.y * v.y + v.z * v.z + v.w * v.w;
    }
    __shared__ float sh0[256], sh1[256];
    sh0[threadIdx.x] = s; sh1[threadIdx.x] = s2;
    __syncthreads();
    for (int off = 128; off > 0; off >>= 1) {
        if (threadIdx.x < off) {
            sh0[threadIdx.x] += sh0[threadIdx.x + off];
            sh1[threadIdx.x] += sh1[threadIdx.x + off];
        }
        __syncthreads();
    }
    if (threadIdx.x == 0) {
        const float inv = 1.f / (float)elems;
        const float mn  = sh0[0] * inv;
        const float var = sh1[0] * inv - mn * mn;
        invstd[bh] = rsqrtf(var + 1e-5f);
    }
}

// ===========================================================================
// row softmax over KV with inv_std scaling; quantizes A inline (max prob = rs)
// ===========================================================================
__global__ __launch_bounds__(256) void softmax_kernel(
    const float* __restrict__ S, const float* __restrict__ invstd,
    int8_t* __restrict__ Ahi, int8_t* __restrict__ Alo,
    float* __restrict__ Ascale, int d, int KV)
{
    const long long row = blockIdx.x;           // bh*d + e
    const int bh = (int)(row / d);
    const float is = invstd[bh];
    const float* p = S + row * KV;
    const long long ob = row * KV;
    const int tid = threadIdx.x;

    float vals[4];
    int cnt = 0;
    float mx = -1e30f;
    for (int i = tid; i < KV; i += 256) {
        const float v = p[i] * is;
        vals[cnt++] = v;
        mx = fmaxf(mx, v);
    }
    __shared__ float sh[256];
    sh[tid] = mx; __syncthreads();
    for (int off = 128; off > 0; off >>= 1) {
        if (tid < off) sh[tid] = fmaxf(sh[tid], sh[tid + off]);
        __syncthreads();
    }
    mx = sh[0];
    __syncthreads();

    float s = 0.f;
    for (int c = 0; c < cnt; c++) { vals[c] = __expf(vals[c] - mx); s += vals[c]; }
    sh[tid] = s; __syncthreads();
    for (int off = 128; off > 0; off >>= 1) {
        if (tid < off) sh[tid] += sh[tid + off];
        __syncthreads();
    }
    const float rs = 1.f / sh[0];
    // quantize: max prob = rs exactly -> scale = rs/127
    const float qs  = rs * (1.0f / 127.0f);
    const float qin = 127.0f / rs;
    if (tid == 0) Ascale[row] = qs;
    cnt = 0;
    for (int i = tid; i < KV; i += 256) {
        const float prob = vals[cnt++] * rs;
        const float h = clamp127(rintf(prob * qin));
        const float r = prob - h * qs;
        const float l = clamp127(rintf(r * qin * 128.0f));
        Ahi[ob + i] = (int8_t)(int)h;
        Alo[ob + i] = (int8_t)(int)l;
    }
}

// ===========================================================================
// head-mean + transpose + quantize: Cm[b][n][e] = 0.25*sum_h C[b*4+h][e][n]
// one block per (b, 32 n); dynamic smem tile[32][d+1].
// ===========================================================================
__global__ void headmean_kernel(
    const float* __restrict__ C, int8_t* __restrict__ Cmhi,
    int8_t* __restrict__ Cmlo, float* __restrict__ Cmscale, int d, int N)
{
    extern __shared__ float smf[];
    float* tile = smf;                     // 32 * (d+1)
    float* red  = tile + 32 * (d + 1);     // 32 * 8
    float* srow = red + 256;               // 32 (scale)
    float* sinv = srow + 32;               // 32 (inv)

    const int b  = blockIdx.z;
    const int n0 = blockIdx.x * 32;
    const int tx = threadIdx.x, ty = threadIdx.y;

    for (int e = ty; e < d; e += 8) {
        float acc = 0.f;
#pragma unroll
        for (int h = 0; h < 4; h++)
            acc += C[(((long long)(b * 4 + h) * d + e) * N) + n0 + tx];
        tile[tx * (d + 1) + e] = 0.25f * acc;
    }
    __syncthreads();

    float mv = 0.f;
    for (int e = ty; e < d; e += 8) mv = fmaxf(mv, fabsf(tile[tx * (d + 1) + e]));
    red[tx * 8 + ty] = mv;
    __syncthreads();
    if (ty == 0) {
        float m = 0.f;
#pragma unroll
        for (int j = 0; j < 8; j++) m = fmaxf(m, red[tx * 8 + j]);
        const float s = m * (1.0f / 127.0f);
        srow[tx] = s;
        sinv[tx] = (m > 0.f) ? (127.0f / m) : 0.f;
        Cmscale[(long long)b * N + n0 + tx] = s;
    }
    __syncthreads();

    const float s = srow[tx], inv = sinv[tx];
    const long long rb = ((long long)b * N + n0 + tx) * d;
    for (int e = ty; e < d; e += 8) {
        const float v = tile[tx * (d + 1) + e];
        const float h = clamp127(rintf(v * inv));
        const float r = v - h * s;
        const float l = clamp127(rintf(r * inv * 128.0f));
        Cmhi[rb + e] = (int8_t)(int)h;
        Cmlo[rb + e] = (int8_t)(int)l;
    }
}

// ===========================================================================
extern "C" void kernel_launch(void* const* d_in, const int* in_sizes, int n_in,
                              void* d_out, int out_size)
{
    (void)in_sizes; (void)n_in; (void)out_size;
    const float* emb[4]  = {(const float*)d_in[0], (const float*)d_in[1],
                            (const float*)d_in[2], (const float*)d_in[3]};
    const float* emb_all = (const float*)d_in[4];
    const float* WQ[4]   = {(const float*)d_in[5], (const float*)d_in[6],
                            (const float*)d_in[7], (const float*)d_in[8]};
    const float* WK      = (const float*)d_in[9];
    const float* WV      = (const float*)d_in[10];
    const float* WO[4]   = {(const float*)d_in[11], (const float*)d_in[12],
                            (const float*)d_in[13], (const float*)d_in[14]};
    float* out = (float*)d_out;

    int8_t *qemb[4], *qemba, *qwq[4], *qwk, *qwv, *qwo[4], *qkt, *qv, *qq, *qa, *qcm;
    float *semb[4], *semba, *swq[4], *swk, *swv, *swo[4], *skt, *sv, *sq, *sa, *scm;
    float *TMP, *S, *C, *invstd;
    cudaGetSymbolAddress((void**)&qemb[0], g_q_emb1);
    cudaGetSymbolAddress((void**)&qemb[1], g_q_emb2);
    cudaGetSymbolAddress((void**)&qemb[2], g_q_emb3);
    cudaGetSymbolAddress((void**)&qemb[3], g_q_emb4);
    cudaGetSymbolAddress((void**)&qemba,   g_q_emba);
    cudaGetSymbolAddress((void**)&qwq[0],  g_q_wq1);
    cudaGetSymbolAddress((void**)&qwq[1],  g_q_wq2);
    cudaGetSymbolAddress((void**)&qwq[2],  g_q_wq3);
    cudaGetSymbolAddress((void**)&qwq[3],  g_q_wq4);
    cudaGetSymbolAddress((void**)&qwk,     g_q_wk);
    cudaGetSymbolAddress((void**)&qwv,     g_q_wv);
    cudaGetSymbolAddress((void**)&qwo[0],  g_q_wo1);
    cudaGetSymbolAddress((void**)&qwo[1],  g_q_wo2);
    cudaGetSymbolAddress((void**)&qwo[2],  g_q_wo3);
    cudaGetSymbolAddress((void**)&qwo[3],  g_q_wo4);
    cudaGetSymbolAddress((void**)&qkt,     g_q_kt);
    cudaGetSymbolAddress((void**)&qv,      g_q_v);
    cudaGetSymbolAddress((void**)&qq,      g_q_q);
    cudaGetSymbolAddress((void**)&qa,      g_q_a);
    cudaGetSymbolAddress((void**)&qcm,     g_q_cm);
    cudaGetSymbolAddress((void**)&semb[0], g_s_emb1);
    cudaGetSymbolAddress((void**)&semb[1], g_s_emb2);
    cudaGetSymbolAddress((void**)&semb[2], g_s_emb3);
    cudaGetSymbolAddress((void**)&semb[3], g_s_emb4);
    cudaGetSymbolAddress((void**)&semba,   g_s_emba);
    cudaGetSymbolAddress((void**)&swq[0],  g_s_wq1);
    cudaGetSymbolAddress((void**)&swq[1],  g_s_wq2);
    cudaGetSymbolAddress((void**)&swq[2],  g_s_wq3);
    cudaGetSymbolAddress((void**)&swq[3],  g_s_wq4);
    cudaGetSymbolAddress((void**)&swk,     g_s_wk);
    cudaGetSymbolAddress((void**)&swv,     g_s_wv);
    cudaGetSymbolAddress((void**)&swo[0],  g_s_wo1);
    cudaGetSymbolAddress((void**)&swo[1],  g_s_wo2);
    cudaGetSymbolAddress((void**)&swo[2],  g_s_wo3);
    cudaGetSymbolAddress((void**)&swo[3],  g_s_wo4);
    cudaGetSymbolAddress((void**)&skt,     g_s_kt);
    cudaGetSymbolAddress((void**)&sv,      g_s_v);
    cudaGetSymbolAddress((void**)&sq,      g_s_q);
    cudaGetSymbolAddress((void**)&sa,      g_s_a);
    cudaGetSymbolAddress((void**)&scm,     g_s_cm);
    cudaGetSymbolAddress((void**)&TMP,     g_TMP);
    cudaGetSymbolAddress((void**)&S,       g_S);
    cudaGetSymbolAddress((void**)&C,       g_C);
    cudaGetSymbolAddress((void**)&invstd,  g_invstd);

    cudaFuncSetAttribute(gemm_i8, cudaFuncAttributeMaxDynamicSharedMemorySize, DYN_SMEM);
    cudaFuncSetAttribute(headmean_kernel, cudaFuncAttributeMaxDynamicSharedMemorySize,
                         (32 * 513 + 256 + 64) * 4);

    const int Bsz = 8, H = 4, Nn = 1024, KV = 960;
    const int df[4] = {64, 128, 256, 512};
    const float scale = 1.0f / sqrtf((float)KV);

    long long outOff[4];
    outOff[0] = 0;
    for (int i = 1; i < 4; i++) outOff[i] = outOff[i-1] + (long long)Bsz * Nn * df[i-1];

    // element counts for hi/lo split offsets
    const long long eEmb[4] = {R_EMB*64, R_EMB*128, R_EMB*256, R_EMB*512};
    const long long eWQ[4]  = {4LL*64*64, 4LL*128*128, 4LL*256*256, 4LL*512*512};
    const long long eWO[4]  = {64LL*64, 128LL*128, 256LL*256, 512LL*512};

    auto quant = [&](const float* src, int8_t* q, long long elems, float* sc,
                     long long rows, int K) {
        quant_rows<<<(unsigned)rows, 128>>>(src, q, q + elems, sc, K);
    };

    // ---- input quantization ----------------------------------------------
    for (int i = 0; i < 4; i++) quant(emb[i], qemb[i], eEmb[i], semb[i], R_EMB, df[i]);
    quant(emb_all, qemba, N_EMBA, semba, R_EMB, KV);
    for (int i = 0; i < 4; i++) quant(WQ[i], qwq[i], eWQ[i], swq[i], 4LL*df[i], df[i]);
    quant(WK, qwk, N_WK, swk, 3840, KV);
    quant(WV, qwv, N_WK, swv, 3840, KV);
    for (int i = 0; i < 4; i++) quant(WO[i], qwo[i], eWO[i], swo[i], df[i], df[i]);

    auto gemm = [&](const int8_t* Aq, long long ae, const float* sA,
                    const int8_t* Bq, long long be, const float* sB,
                    float* Cf, int M, int N, int K,
                    long long aS, long long bS, long long aSS, long long bSS,
                    int mA, int mB, int Hh, int Z, float al) {
        dim3 g((unsigned)((N + BN - 1) / BN), (unsigned)((M + BM - 1) / BM), (unsigned)Z);
        gemm_i8<<<g, NTHREADS, DYN_SMEM>>>(Aq, Aq + ae, Bq, Bq + be, sA, sB, Cf,
                                           M, N, K, aS, bS, aSS, bSS, mA, mB, Hh, al);
    };

    // KT[z][j][n] = WK_h @ emb_all_b^T :  M=960, N=1024, K=960
    gemm(qwk, N_WK, swk, qemba, N_EMBA, semba, TMP,
         KV, Nn, KV, 960LL*960, 1024LL*960, 960, 1024, 2, 1, H, Bsz*H, 1.f);
    quant(TMP, qkt, N_KT, skt, 32LL*960, Nn);

    // V[z][n][j] = emb_all_b @ WV_h^T :  M=1024, N=960, K=960
    gemm(qemba, N_EMBA, semba, qwv, N_WK, swv, TMP,
         Nn, KV, KV, 1024LL*960, 960LL*960, 1024, 960, 1, 2, H, Bsz*H, 1.f);
    quant(TMP, qv, N_VV, sv, 32LL*1024, KV);

    for (int br = 0; br < 4; br++) {
        const int d = df[br];
        const long long qRows = 32LL * d;

        // Q[z][e][n] = WQ_h @ emb_b^T :  M=d, N=1024, K=d
        gemm(qwq[br], eWQ[br], swq[br], qemb[br], eEmb[br], semb[br], TMP,
             d, Nn, d, (long long)d*d, 1024LL*d, d, 1024, 2, 1, H, Bsz*H, 1.f);
        quant(TMP, qq, N_Qmx, sq, qRows, Nn);

        // S[z][e][j] = scale * Q @ KT^T :  M=d, N=960, K=1024
        gemm(qq, N_Qmx, sq, qkt, N_KT, skt, S,
             d, KV, Nn, (long long)d*1024, 960LL*1024, d, 960, 3, 3, H, Bsz*H, scale);

        stats_kernel<<<Bsz*H, 256>>>(S, invstd, d * KV);
        softmax_kernel<<<Bsz*H*d, 256>>>(S, invstd, qa, qa + N_Amx, sa, d, KV);

        // C[z][e][n] = A @ V^T :  M=d, N=1024, K=960
        gemm(qa, N_Amx, sa, qv, N_VV, sv, C,
             d, Nn, KV, (long long)d*960, 1024LL*960, d, 1024, 3, 3, H, Bsz*H, 1.f);

        // Cm[b][n][e] (quantized) = 0.25 * sum_h C
        {
            dim3 g((unsigned)(Nn / 32), 1, (unsigned)Bsz);
            const int smem = (32 * (d + 1) + 256 + 64) * 4;
            headmean_kernel<<<g, dim3(32, 8, 1), smem>>>(C, qcm, qcm + N_CMmx, scm, d, Nn);
        }

        // O[b][n][f] = Cm @ WO^T :  M=1024, N=d, K=d
        gemm(qcm, N_CMmx, scm, qwo[br], eWO[br], swo[br], out + outOff[br],
             Nn, d, d, 1024LL*d, 0LL, 1024, 0, 3, 0, 1, Bsz, 1.f);
    }
}

// round 15
// speedup vs baseline: 2.4420x; 2.4420x over previous
#include <cuda_runtime.h>
#include <cuda_bf16.h>
#include <cstdint>
#include <cmath>

// ===========================================================================
// MultiheadChannelAttention — Round 11: R9 bf16x3 HMMA engine (at legacy-HMMA
// issue ceiling) + S-GEMM epilogue variance partials (deterministic slots) +
// invstd folded into softmax. Launches 31 -> 27, stats pass eliminated.
// All GEMMs NT: C[M,N] = alpha * A[M,K] @ B[N,K]^T, operands bf16 (hi,lo);
// C = Ahi*Bhi + Ahi*Blo + Alo*Bhi, fp32 accum.
// ===========================================================================

// ------------------------- sizes (elements) --------------------------------
constexpr long long N_EMB1 = 8LL*1024*64;
constexpr long long N_EMB2 = 8LL*1024*128;
constexpr long long N_EMB3 = 8LL*1024*256;
constexpr long long N_EMB4 = 8LL*1024*512;
constexpr long long N_EMBA = 8LL*1024*960;
constexpr long long N_WQ1 = 4LL*64*64;
constexpr long long N_WQ2 = 4LL*128*128;
constexpr long long N_WQ3 = 4LL*256*256;
constexpr long long N_WQ4 = 4LL*512*512;
constexpr long long N_WK  = 4LL*960*960;
constexpr long long N_WV  = 4LL*960*960;
constexpr long long N_WO1 = 64LL*64;
constexpr long long N_WO2 = 128LL*128;
constexpr long long N_WO3 = 256LL*256;
constexpr long long N_WO4 = 512LL*512;
constexpr long long N_KT  = 32LL*960*1024;
constexpr long long N_VV  = 32LL*1024*960;
constexpr long long N_Q1  = 32LL*64*1024;
constexpr long long N_Q2  = 32LL*128*1024;
constexpr long long N_Q3  = 32LL*256*1024;
constexpr long long N_Q4  = 32LL*512*1024;
constexpr long long N_A   = 32LL*512*960;
constexpr long long N_CC  = 32LL*512*1024;
constexpr long long N_CM  = 8LL*1024*512;

// ------------------------- device scratch (hi at [0..n), lo at [n..2n)) ----
__device__ __align__(128) __nv_bfloat16 g_emb1p[2*N_EMB1];
__device__ __align__(128) __nv_bfloat16 g_emb2p[2*N_EMB2];
__device__ __align__(128) __nv_bfloat16 g_emb3p[2*N_EMB3];
__device__ __align__(128) __nv_bfloat16 g_emb4p[2*N_EMB4];
__device__ __align__(128) __nv_bfloat16 g_embap[2*N_EMBA];
__device__ __align__(128) __nv_bfloat16 g_wq1p[2*N_WQ1];
__device__ __align__(128) __nv_bfloat16 g_wq2p[2*N_WQ2];
__device__ __align__(128) __nv_bfloat16 g_wq3p[2*N_WQ3];
__device__ __align__(128) __nv_bfloat16 g_wq4p[2*N_WQ4];
__device__ __align__(128) __nv_bfloat16 g_wkp [2*N_WK];
__device__ __align__(128) __nv_bfloat16 g_wvp [2*N_WV];
__device__ __align__(128) __nv_bfloat16 g_wo1p[2*N_WO1];
__device__ __align__(128) __nv_bfloat16 g_wo2p[2*N_WO2];
__device__ __align__(128) __nv_bfloat16 g_wo3p[2*N_WO3];
__device__ __align__(128) __nv_bfloat16 g_wo4p[2*N_WO4];
__device__ __align__(128) __nv_bfloat16 g_ktp [2*N_KT];
__device__ __align__(128) __nv_bfloat16 g_vp  [2*N_VV];
__device__ __align__(128) __nv_bfloat16 g_q1p [2*N_Q1];
__device__ __align__(128) __nv_bfloat16 g_q2p [2*N_Q2];
__device__ __align__(128) __nv_bfloat16 g_q3p [2*N_Q3];
__device__ __align__(128) __nv_bfloat16 g_q4p [2*N_Q4];
__device__ __align__(128) __nv_bfloat16 g_ap  [2*N_A];
__device__ __align__(128) __nv_bfloat16 g_cmp [2*N_CM];
__device__ float g_S[N_A];      // fp32 scores (per-branch reuse)
__device__ float g_C[N_CC];     // fp32 context (per-branch reuse)
__device__ float g_part1[32*64];  // per-(z,tile) sum partials
__device__ float g_part2[32*64];  // per-(z,tile) sum-of-squares partials

// ------------------------- helpers -----------------------------------------
__device__ __forceinline__ uint32_t smem_u32(const void* p){
    uint32_t a;
    asm("{ .reg .u64 t; cvta.to.shared.u64 t, %1; cvt.u32.u64 %0, t; }"
        : "=r"(a) : "l"(p));
    return a;
}
__device__ __forceinline__ void ldsm_x4(uint32_t a, uint32_t& r0, uint32_t& r1,
                                        uint32_t& r2, uint32_t& r3){
    asm volatile("ldmatrix.sync.aligned.m8n8.x4.shared.b16 {%0,%1,%2,%3}, [%4];"
                 : "=r"(r0), "=r"(r1), "=r"(r2), "=r"(r3) : "r"(a));
}
__device__ __forceinline__ void mma_bf16(float* c, const uint32_t* a,
                                         uint32_t b0, uint32_t b1){
    asm volatile(
        "mma.sync.aligned.m16n8k16.row.col.f32.bf16.bf16.f32 "
        "{%0,%1,%2,%3}, {%4,%5,%6,%7}, {%8,%9}, {%0,%1,%2,%3};"
        : "+f"(c[0]), "+f"(c[1]), "+f"(c[2]), "+f"(c[3])
        : "r"(a[0]), "r"(a[1]), "r"(a[2]), "r"(a[3]), "r"(b0), "r"(b1));
}

// ------------------------- tile geometry -----------------------------------
constexpr int BM = 128, BN = 128;
constexpr int ROWB = 80;                           // 64B data + 16B pad per row
constexpr int MAT = 128 * ROWB;                    // 10240 B per matrix tile
constexpr int OFF_AH = 0;
constexpr int OFF_AL = MAT;
constexpr int OFF_BH = 2 * MAT;
constexpr int OFF_BL = 3 * MAT;
constexpr int STAGE_BYTES = 4 * MAT;               // 40960 B
constexpr int DYN_SMEM = 2 * STAGE_BYTES;          // 81920 B
constexpr int NTHREADS = 256;

// ===========================================================================
// bf16x3 batched NT GEMM via mma.sync. z-mode: 0 shared, 1 z/H, 2 z%H, 3 z.
// 8 warps (2m x 4n), warp tile 64x32, 2 CTAs/SM.
// When part1/part2 != null (S GEMM) each CTA stores its tile's (sum, sum2)
// of the written values to slot [z*64 + tileIdx] — fixed slots, deterministic.
// ===========================================================================
__global__ __launch_bounds__(NTHREADS, 2)
void gemm_bf16x3(
    const __nv_bfloat16* __restrict__ Ahi, const __nv_bfloat16* __restrict__ Alo,
    const __nv_bfloat16* __restrict__ Bhi, const __nv_bfloat16* __restrict__ Blo,
    float* __restrict__ Cf, __nv_bfloat16* __restrict__ Chi, __nv_bfloat16* __restrict__ Clo,
    float* __restrict__ part1, float* __restrict__ part2,
    int M, int N, int K,
    long long aStride, long long bStride,
    int modeA, int modeB, int H, float alpha)
{
    extern __shared__ char dynsmem[];
    __shared__ float sred[NTHREADS];
    const uint32_t sb = smem_u32(dynsmem);

    const int tid  = threadIdx.x;
    const int wid  = tid >> 5;
    const int lane = tid & 31;
    const int wm   = wid >> 2;            // 0..1 -> m offset 64*wm
    const int wn   = wid & 3;             // 0..3 -> n offset 32*wn

    const int z  = blockIdx.z;
    const int zA = (modeA == 0) ? 0 : (modeA == 1) ? (z / H) : (modeA == 2) ? (z % H) : z;
    const int zB = (modeB == 0) ? 0 : (modeB == 1) ? (z / H) : (modeB == 2) ? (z % H) : z;
    const __nv_bfloat16* pA[2] = { Ahi + (long long)zA * aStride, Alo + (long long)zA * aStride };
    const __nv_bfloat16* pB[2] = { Bhi + (long long)zB * bStride, Blo + (long long)zB * bStride };

    const int m0 = blockIdx.y * BM;
    const int n0 = blockIdx.x * BN;
    const int NC = K >> 5;                // chunks of 32

    auto load_stage = [&](int stage, int kc) {
        const int k0 = kc << 5;
        const uint32_t stb = sb + (uint32_t)(stage * STAGE_BYTES);
#pragma unroll
        for (int it = 0; it < 8; ++it) {
            const int idx = it * NTHREADS + tid;     // 0..2047
            const int mat = idx >> 9;                // 0..3: AH, AL, BH, BL
            const int rem = idx & 511;
            const int row = rem >> 2;                // 0..127
            const int seg = rem & 3;                 // 16B segment
            int g, lim; const __nv_bfloat16* src;
            if (mat < 2) { g = m0 + row; lim = M; src = pA[mat]; }
            else         { g = n0 + row; lim = N; src = pB[mat - 2]; }
            const int valid = (g < lim);
            const uint32_t dst = stb + (uint32_t)(mat * MAT) + (uint32_t)(row * ROWB + seg * 16);
            const char* sp = (const char*)(src + (long long)(valid ? g : 0) * K + k0 + seg * 8);
            const uint32_t sz = valid ? 16u : 0u;
            asm volatile("cp.async.cg.shared.global [%0], [%1], 16, %2;"
                         :: "r"(dst), "l"(sp), "r"(sz));
        }
        asm volatile("cp.async.commit_group;" ::: "memory");
    };

    float acc[4][4][4];                   // [mt][nsub][frag] = 64 regs
#pragma unroll
    for (int t = 0; t < 4; t++)
#pragma unroll
        for (int n = 0; n < 4; n++)
#pragma unroll
            for (int j = 0; j < 4; j++) acc[t][n][j] = 0.f;

    load_stage(0, 0);
    if (NC > 1) load_stage(1, 1);

    const uint32_t lrow = (uint32_t)(lane & 15) * ROWB;
    const uint32_t lseg = (uint32_t)(lane >> 4) * 16;

    for (int kc = 0; kc < NC; ++kc) {
        if (kc + 2 <= NC) { asm volatile("cp.async.wait_group 1;" ::: "memory"); }
        else              { asm volatile("cp.async.wait_group 0;" ::: "memory"); }
        __syncthreads();

        const int st = kc & 1;
        const uint32_t stb = sb + (uint32_t)(st * STAGE_BYTES);
        const uint32_t aHb = stb + OFF_AH, aLb = stb + OFF_AL;
        const uint32_t bHb = stb + OFF_BH, bLb = stb + OFF_BL;

#pragma unroll
        for (int kk = 0; kk < 2; ++kk) {
            const uint32_t koff = (uint32_t)kk * 32 + lseg;
            const uint32_t aro0 = (uint32_t)(wm * 64) * ROWB + lrow + koff;
            const uint32_t bro0 = (uint32_t)(wn * 32) * ROWB + lrow + koff;

            uint32_t aH[4][4], bH[2][4];
#pragma unroll
            for (int t = 0; t < 4; ++t)
                ldsm_x4(aHb + aro0 + (uint32_t)(t * 16) * ROWB,
                        aH[t][0], aH[t][1], aH[t][2], aH[t][3]);
#pragma unroll
            for (int p = 0; p < 2; ++p)
                ldsm_x4(bHb + bro0 + (uint32_t)(p * 16) * ROWB,
                        bH[p][0], bH[p][1], bH[p][2], bH[p][3]);

            // pass 1: Ahi * Bhi
#pragma unroll
            for (int p = 0; p < 2; ++p)
#pragma unroll
                for (int t = 0; t < 4; ++t) {
                    mma_bf16(acc[t][2*p],   aH[t], bH[p][0], bH[p][2]);
                    mma_bf16(acc[t][2*p+1], aH[t], bH[p][1], bH[p][3]);
                }

            uint32_t bL[2][4];
#pragma unroll
            for (int p = 0; p < 2; ++p)
                ldsm_x4(bLb + bro0 + (uint32_t)(p * 16) * ROWB,
                        bL[p][0], bL[p][1], bL[p][2], bL[p][3]);

            // pass 2: Ahi * Blo
#pragma unroll
            for (int p = 0; p < 2; ++p)
#pragma unroll
                for (int t = 0; t < 4; ++t) {
                    mma_bf16(acc[t][2*p],   aH[t], bL[p][0], bL[p][2]);
                    mma_bf16(acc[t][2*p+1], aH[t], bL[p][1], bL[p][3]);
                }

            uint32_t aL[4][4];
#pragma unroll
            for (int t = 0; t < 4; ++t)
                ldsm_x4(aLb + aro0 + (uint32_t)(t * 16) * ROWB,
                        aL[t][0], aL[t][1], aL[t][2], aL[t][3]);

            // pass 3: Alo * Bhi
#pragma unroll
            for (int p = 0; p < 2; ++p)
#pragma unroll
                for (int t = 0; t < 4; ++t) {
                    mma_bf16(acc[t][2*p],   aL[t], bH[p][0], bH[p][2]);
                    mma_bf16(acc[t][2*p+1], aL[t], bH[p][1], bH[p][3]);
                }
        }
        __syncthreads();
        if (kc + 2 < NC) load_stage(st, kc + 2);
    }

    // ------- epilogue ------------------------------------------------------
    const int grp  = lane >> 2;
    const int tid4 = lane & 3;
    float ls = 0.f, ls2 = 0.f;
#pragma unroll
    for (int t = 0; t < 4; ++t) {
#pragma unroll
        for (int n = 0; n < 4; ++n) {
            const int gn = n0 + wn * 32 + n * 8 + tid4 * 2;
            if (gn >= N) continue;
#pragma unroll
            for (int half = 0; half < 2; ++half) {
                const int gm = m0 + wm * 64 + t * 16 + grp + half * 8;
                if (gm >= M) continue;
                const float v0 = alpha * acc[t][n][half * 2 + 0];
                const float v1 = alpha * acc[t][n][half * 2 + 1];
                const long long base = (long long)z * M * N + (long long)gm * N + gn;
                if (Cf) {
                    *reinterpret_cast<float2*>(Cf + base) = make_float2(v0, v1);
                    ls  += v0 + v1;
                    ls2 += v0 * v0 + v1 * v1;
                } else {
                    __nv_bfloat162 hp = __floats2bfloat162_rn(v0, v1);
                    __nv_bfloat162 lp = __floats2bfloat162_rn(v0 - __bfloat162float(hp.x),
                                                              v1 - __bfloat162float(hp.y));
                    *reinterpret_cast<__nv_bfloat162*>(Chi + base) = hp;
                    *reinterpret_cast<__nv_bfloat162*>(Clo + base) = lp;
                }
            }
        }
    }

    if (part1) {
        // deterministic block reduction (fixed tree order)
        sred[tid] = ls; __syncthreads();
        for (int off = NTHREADS / 2; off > 0; off >>= 1) {
            if (tid < off) sred[tid] += sred[tid + off];
            __syncthreads();
        }
        const float tsum = sred[0];
        __syncthreads();
        sred[tid] = ls2; __syncthreads();
        for (int off = NTHREADS / 2; off > 0; off >>= 1) {
            if (tid < off) sred[tid] += sred[tid + off];
            __syncthreads();
        }
        if (tid == 0) {
            const int tileIdx = blockIdx.y * gridDim.x + blockIdx.x;
            part1[z * 64 + tileIdx] = tsum;
            part2[z * 64 + tileIdx] = sred[0];
        }
    }
}

// ===========================================================================
// merged split: fp32 -> bf16 (hi, lo) for all input tensors in one launch.
// ===========================================================================
struct SplitJobs {
    const float* src[15];
    __nv_bfloat16* hi[15];
    __nv_bfloat16* lo[15];
    long long cnt[15];
};

__global__ __launch_bounds__(256) void split_all_kernel(SplitJobs jobs)
{
    const int j = blockIdx.y;
    const float* __restrict__ src = jobs.src[j];
    __nv_bfloat16* __restrict__ hi = jobs.hi[j];
    __nv_bfloat16* __restrict__ lo = jobs.lo[j];
    const long long n = jobs.cnt[j];
    long long i = (long long)blockIdx.x * blockDim.x + threadIdx.x;
    const long long stride = (long long)gridDim.x * blockDim.x;
    for (; i < n; i += stride) {
        const float x = src[i];
        const __nv_bfloat16 h = __float2bfloat16(x);
        hi[i] = h;
        lo[i] = __float2bfloat16(x - __bfloat162float(h));
    }
}

// ===========================================================================
// row softmax over KV. invstd computed inline from the S-GEMM tile partials
// (sum over nTiles fixed slots -> biased variance; mean cancels in softmax).
// Writes bf16 (hi, lo) pair.
// ===========================================================================
__global__ __launch_bounds__(256) void softmax_kernel(
    const float* __restrict__ S,
    const float* __restrict__ part1, const float* __restrict__ part2,
    int nTiles,
    __nv_bfloat16* __restrict__ Ahi, __nv_bfloat16* __restrict__ Alo,
    int d, int KV)
{
    const long long row = blockIdx.x;           // bh*d + e
    const int bh = (int)(row / d);
    const float* p = S + row * KV;
    const long long ob = row * KV;
    const int tid = threadIdx.x;

    __shared__ float sh[256];
    __shared__ float s_invstd;

    // ---- invstd from partials (deterministic fixed-order reduce) ----------
    {
        float a = 0.f, b = 0.f;
        if (tid < nTiles) { a = part1[bh * 64 + tid]; b = part2[bh * 64 + tid]; }
        sh[tid] = a; __syncthreads();
        for (int off = 128; off > 0; off >>= 1) {
            if (tid < off) sh[tid] += sh[tid + off];
            __syncthreads();
        }
        const float sum1 = sh[0];
        __syncthreads();
        sh[tid] = b; __syncthreads();
        for (int off = 128; off > 0; off >>= 1) {
            if (tid < off) sh[tid] += sh[tid + off];
            __syncthreads();
        }
        if (tid == 0) {
            const float inv = 1.0f / (float)(d * KV);
            const float m   = sum1 * inv;
            const float var = sh[0] * inv - m * m;
            s_invstd = rsqrtf(var + 1e-5f);
        }
        __syncthreads();
    }
    const float is = s_invstd;

    float vals[4];
    int cnt = 0;
    float mx = -1e30f;
    for (int i = tid; i < KV; i += 256) {
        const float v = p[i] * is;
        vals[cnt++] = v;
        mx = fmaxf(mx, v);
    }
    sh[tid] = mx; __syncthreads();
    for (int off = 128; off > 0; off >>= 1) {
        if (tid < off) sh[tid] = fmaxf(sh[tid], sh[tid + off]);
        __syncthreads();
    }
    mx = sh[0];
    __syncthreads();

    float s = 0.f;
    for (int c = 0; c < cnt; c++) { vals[c] = __expf(vals[c] - mx); s += vals[c]; }
    sh[tid] = s; __syncthreads();
    for (int off = 128; off > 0; off >>= 1) {
        if (tid < off) sh[tid] += sh[tid + off];
        __syncthreads();
    }
    const float rs = 1.f / sh[0];
    cnt = 0;
    for (int i = tid; i < KV; i += 256) {
        const float a = vals[cnt++] * rs;
        const __nv_bfloat16 h = __float2bfloat16(a);
        Ahi[ob + i] = h;
        Alo[ob + i] = __float2bfloat16(a - __bfloat162float(h));
    }
}

// ===========================================================================
// Cm[b][n][e] = 0.25 * sum_h C[b*4+h][e][n], written as bf16 (hi, lo)
// ===========================================================================
__global__ __launch_bounds__(256) void headmean_kernel(
    const float* __restrict__ C, __nv_bfloat16* __restrict__ Cmhi,
    __nv_bfloat16* __restrict__ Cmlo, int d, int N)
{
    __shared__ float tile[32][33];
    const int b  = blockIdx.z;
    const int e0 = blockIdx.y * 32;
    const int n0 = blockIdx.x * 32;
    const int tx = threadIdx.x, ty = threadIdx.y;

    for (int r = ty; r < 32; r += 8) {
        const int e = e0 + r;
        float acc = 0.f;
#pragma unroll
        for (int h = 0; h < 4; h++)
            acc += C[(((long long)(b * 4 + h) * d + e) * N) + n0 + tx];
        tile[r][tx] = 0.25f * acc;
    }
    __syncthreads();
    for (int r = ty; r < 32; r += 8) {
        const int n = n0 + r;
        const int e = e0 + tx;
        const float v = tile[tx][r];
        const __nv_bfloat16 h = __float2bfloat16(v);
        const long long idx = ((long long)b * N + n) * d + e;
        Cmhi[idx] = h;
        Cmlo[idx] = __float2bfloat16(v - __bfloat162float(h));
    }
}

// ===========================================================================
extern "C" void kernel_launch(void* const* d_in, const int* in_sizes, int n_in,
                              void* d_out, int out_size)
{
    (void)in_sizes; (void)n_in; (void)out_size;
    const float* emb[4]  = {(const float*)d_in[0], (const float*)d_in[1],
                            (const float*)d_in[2], (const float*)d_in[3]};
    const float* emb_all = (const float*)d_in[4];
    const float* WQ[4]   = {(const float*)d_in[5], (const float*)d_in[6],
                            (const float*)d_in[7], (const float*)d_in[8]};
    const float* WK      = (const float*)d_in[9];
    const float* WV      = (const float*)d_in[10];
    const float* WO[4]   = {(const float*)d_in[11], (const float*)d_in[12],
                            (const float*)d_in[13], (const float*)d_in[14]};
    float* out = (float*)d_out;

    __nv_bfloat16 *embp[4], *embap, *wqp[4], *wkp, *wvp, *wop[4];
    __nv_bfloat16 *ktp, *vp, *qp[4], *ap, *cmp;
    float *S, *C, *part1, *part2;
    cudaGetSymbolAddress((void**)&embp[0], g_emb1p);
    cudaGetSymbolAddress((void**)&embp[1], g_emb2p);
    cudaGetSymbolAddress((void**)&embp[2], g_emb3p);
    cudaGetSymbolAddress((void**)&embp[3], g_emb4p);
    cudaGetSymbolAddress((void**)&embap,   g_embap);
    cudaGetSymbolAddress((void**)&wqp[0],  g_wq1p);
    cudaGetSymbolAddress((void**)&wqp[1],  g_wq2p);
    cudaGetSymbolAddress((void**)&wqp[2],  g_wq3p);
    cudaGetSymbolAddress((void**)&wqp[3],  g_wq4p);
    cudaGetSymbolAddress((void**)&wkp,     g_wkp);
    cudaGetSymbolAddress((void**)&wvp,     g_wvp);
    cudaGetSymbolAddress((void**)&wop[0],  g_wo1p);
    cudaGetSymbolAddress((void**)&wop[1],  g_wo2p);
    cudaGetSymbolAddress((void**)&wop[2],  g_wo3p);
    cudaGetSymbolAddress((void**)&wop[3],  g_wo4p);
    cudaGetSymbolAddress((void**)&ktp,     g_ktp);
    cudaGetSymbolAddress((void**)&vp,      g_vp);
    cudaGetSymbolAddress((void**)&qp[0],   g_q1p);
    cudaGetSymbolAddress((void**)&qp[1],   g_q2p);
    cudaGetSymbolAddress((void**)&qp[2],   g_q3p);
    cudaGetSymbolAddress((void**)&qp[3],   g_q4p);
    cudaGetSymbolAddress((void**)&ap,      g_ap);
    cudaGetSymbolAddress((void**)&cmp,     g_cmp);
    cudaGetSymbolAddress((void**)&S,       g_S);
    cudaGetSymbolAddress((void**)&C,       g_C);
    cudaGetSymbolAddress((void**)&part1,   g_part1);
    cudaGetSymbolAddress((void**)&part2,   g_part2);

    cudaFuncSetAttribute(gemm_bf16x3, cudaFuncAttributeMaxDynamicSharedMemorySize, DYN_SMEM);

    const int Bsz = 8, H = 4, Nn = 1024, KV = 960;
    const int df[4] = {64, 128, 256, 512};
    const long long nEmb[4] = {N_EMB1, N_EMB2, N_EMB3, N_EMB4};
    const long long nWQ[4]  = {N_WQ1, N_WQ2, N_WQ3, N_WQ4};
    const long long nWO[4]  = {N_WO1, N_WO2, N_WO3, N_WO4};
    const long long nQ[4]   = {N_Q1, N_Q2, N_Q3, N_Q4};
    const float scale = 1.0f / sqrtf((float)KV);

    long long outOff[4];
    outOff[0] = 0;
    for (int i = 1; i < 4; i++) outOff[i] = outOff[i-1] + (long long)Bsz * Nn * df[i-1];

    // ---- launch 0: merged split of all 15 inputs --------------------------
    {
        SplitJobs jobs;
        const float* srcs[15] = { emb[0], emb[1], emb[2], emb[3], emb_all,
                                  WQ[0], WQ[1], WQ[2], WQ[3], WK, WV,
                                  WO[0], WO[1], WO[2], WO[3] };
        __nv_bfloat16* dsts[15] = { embp[0], embp[1], embp[2], embp[3], embap,
                                    wqp[0], wqp[1], wqp[2], wqp[3], wkp, wvp,
                                    wop[0], wop[1], wop[2], wop[3] };
        const long long cnts[15] = { nEmb[0], nEmb[1], nEmb[2], nEmb[3], N_EMBA,
                                     nWQ[0], nWQ[1], nWQ[2], nWQ[3], N_WK, N_WV,
                                     nWO[0], nWO[1], nWO[2], nWO[3] };
        for (int i = 0; i < 15; i++) {
            jobs.src[i] = srcs[i];
            jobs.hi[i]  = dsts[i];
            jobs.lo[i]  = dsts[i] + cnts[i];
            jobs.cnt[i] = cnts[i];
        }
        split_all_kernel<<<dim3(512, 15, 1), 256>>>(jobs);
    }

    auto gemm = [&](const __nv_bfloat16* Ah, long long an,
                    const __nv_bfloat16* Bh, long long bn,
                    float* Cf, __nv_bfloat16* Ch, long long cn,
                    float* p1, float* p2,
                    int M, int N, int K, long long aS, long long bS,
                    int mA, int mB, int Hh, int Z, float al) {
        dim3 g((unsigned)((N + BN - 1) / BN), (unsigned)((M + BM - 1) / BM), (unsigned)Z);
        gemm_bf16x3<<<g, NTHREADS, DYN_SMEM>>>(Ah, Ah + an, Bh, Bh + bn,
                                               Cf, Ch, Ch ? Ch + cn : nullptr,
                                               p1, p2,
                                               M, N, K, aS, bS, mA, mB, Hh, al);
    };

    auto launchQ = [&](int br) {
        const int d = df[br];
        gemm(wqp[br], nWQ[br], embp[br], nEmb[br], nullptr, qp[br], nQ[br],
             nullptr, nullptr,
             d, Nn, d, (long long)d*d, 1024LL*d, 2, 1, H, Bsz*H, 1.f);
    };
    auto launchS = [&](int br) {
        const int d = df[br];
        gemm(qp[br], nQ[br], ktp, N_KT, S, nullptr, 0,
             part1, part2,
             d, KV, Nn, (long long)d*1024, 960LL*1024, 3, 3, H, Bsz*H, scale);
    };
    auto finishBranch = [&](int br) {
        const int d = df[br];
        const int nTiles = 8 * ((d + 127) / 128);   // gridX(=8 for N=960) * gridY
        softmax_kernel<<<Bsz*H*d, 256>>>(S, part1, part2, nTiles,
                                         ap, ap + N_A, d, KV);
        gemm(ap, N_A, vp, N_VV, C, nullptr, 0, nullptr, nullptr,
             d, Nn, KV, (long long)d*960, 1024LL*960, 3, 3, H, Bsz*H, 1.f);
        dim3 g((unsigned)(Nn / 32), (unsigned)(d / 32), (unsigned)Bsz);
        headmean_kernel<<<g, dim3(32, 8, 1)>>>(C, cmp, cmp + N_CM, d, Nn);
        gemm(cmp, N_CM, wop[br], nWO[br], out + outOff[br], nullptr, 0,
             nullptr, nullptr,
             Nn, d, d, 1024LL*d, 0LL, 3, 0, 1, Bsz, 1.f);
    };

    // launches 1,2: KT, V (big GEMMs)
    gemm(wkp, N_WK, embap, N_EMBA, nullptr, ktp, N_KT, nullptr, nullptr,
         KV, Nn, KV, 960LL*960, 1024LL*960, 2, 1, H, Bsz*H, 1.f);
    gemm(embap, N_EMBA, wvp, N_WV, nullptr, vp, N_VV, nullptr, nullptr,
         Nn, KV, KV, 1024LL*960, 960LL*960, 1, 2, H, Bsz*H, 1.f);

    // launches 3,4,5: Q(512), S(512), Q(256) — GEMMs around ncu -s 5
    launchQ(3);
    launchS(3);
    launchQ(2);

    finishBranch(3);
    launchS(2);
    launchQ(1);
    finishBranch(2);
    launchS(1);
    launchQ(0);
    finishBranch(1);
    launchS(0);
    finishBranch(0);
}